// round 5
// baseline (speedup 1.0000x reference)
#include <cuda_runtime.h>
#include <stdint.h>
#include <math.h>

#define FMASK 0xffffffffu

static __device__ __forceinline__ float ex2f(float x){ float y; asm("ex2.approx.f32 %0, %1;" : "=f"(y) : "f"(x)); return y; }
static __device__ __forceinline__ float lg2f(float x){ float y; asm("lg2.approx.f32 %0, %1;" : "=f"(y) : "f"(x)); return y; }
static __device__ __forceinline__ float rcpf(float x){ float y; asm("rcp.approx.f32 %0, %1;" : "=f"(y) : "f"(x)); return y; }
static __device__ __forceinline__ void cp16(uint32_t dst, const void* src){
    asm volatile("cp.async.cg.shared.global [%0], [%1], 16;" :: "r"(dst), "l"(src) : "memory");
}
static __device__ __forceinline__ void cpcommit(){ asm volatile("cp.async.commit_group;" ::: "memory"); }
static __device__ __forceinline__ void cpwait14(){ asm volatile("cp.async.wait_group 14;" ::: "memory"); }
static __device__ __forceinline__ void barsync(int id){ asm volatile("bar.sync %0, 256;" :: "r"(id) : "memory"); }
static __device__ __forceinline__ void bararrive(int id){ asm volatile("bar.arrive %0, 256;" :: "r"(id) : "memory"); }
static __device__ __forceinline__ void membar_cta(){ asm volatile("membar.cta;" ::: "memory"); }

// Named barriers: 1,2 = "chunk full" (ping/pong), 3,4 = "chunk empty" (ping/pong)
// Warp roles (SMSP = w % 4, hi-wid-first arbitration):
//   w4 = scan (SMSP0, highest wid there -> priority)
//   w0 = scalar lq/lp (SMSP0)
//   w1,w5 (SMSP1), w2,w6 (SMSP2) = A expansion
//   w3,w7 (SMSP3) = B expansion

__global__ __launch_bounds__(256, 1)
void dynparam_kernel(const float* __restrict__ logits,
                     const float* __restrict__ gum,
                     const float* __restrict__ Amat,
                     const float* __restrict__ Bmat,
                     const float* __restrict__ Cmat,
                     const float* __restrict__ transP,
                     float* __restrict__ out)
{
    constexpr int T = 1024;
    constexpr float SCALE = 2.8853900817779268f;   // (1/tau)*log2(e), tau = 0.5
    constexpr float LOG2E = 1.4426950408889634f;
    constexpr float LN2   = 0.6931471805599453f;

    __shared__ __align__(16) float ring[16*256];    // logits ring, 16 slots (15 ahead)
    __shared__ __align__(16) float gring[16*16];    // gumbel ring
    __shared__ __align__(16) float ebuf[2*32*16];   // ping-pong: unnormalized e per step
    __shared__ __align__(16) float ubuf[2*32*16];   // ping-pong: raw mixed logit u per step
    __shared__ __align__(16) float rbuf[2*32];      // ping-pong: r_t = 1/S_t per step
    __shared__ __align__(16) float4 lgPs4[64];      // log(transP), 16x16 as float4

    const int b = blockIdx.x;
    const int tid = threadIdx.x;
    const int w = tid >> 5;
    const int lane = tid & 31;

    float* outA  = out;                 // (B,T,16,16)
    float* outB  = out + 33554432u;     // (B,T,16,8)
    float* outC  = out + 50331648u;     // (B,1,32,16)
    float* outLq = out + 50397184u;     // (B,T)
    float* outLp = out + 50528256u;     // (B,T)

    if (w == 4) {
        // ---------------- scan (producer) warp, SMSP0, highest wid ----------------
        const int j = lane & 15;
        const int kbase = (lane >> 4) * 8;       // low lanes: rows 0..7, high: 8..15
        const bool wr = (lane < 16);
        const float* Lrow = logits + (size_t)b * ((size_t)T * 256);
        const float* grow = gum    + (size_t)b * ((size_t)T * 16);
        uint32_t ring_b  = (uint32_t)__cvta_generic_to_shared(ring);
        uint32_t gring_b = (uint32_t)__cvta_generic_to_shared(gring);

        // prologue: prefetch steps 0..14
        #pragma unroll
        for (int pt = 0; pt < 15; ++pt) {
            uint32_t sb = ring_b + pt*1024 + lane*16;
            const float* gp = Lrow + pt*256 + lane*4;
            cp16(sb, gp);
            cp16(sb + 512, gp + 128);
            if (lane < 4) cp16(gring_b + pt*64 + lane*16, grow + pt*16 + lane*4);
            cpcommit();
        }
        cpwait14();            // slot 0 complete
        __syncwarp();

        float Lc[8], ea[8], eb[8];
        #pragma unroll
        for (int i = 0; i < 8; ++i) { Lc[i] = ring[(kbase + i)*16 + j]; ea[i] = 1.0f; }
        float gC = gring[j] * SCALE;
        float rC = 0.0625f * SCALE;   // SCALE / S_prev  (y0 uniform => e=1, S=16)

#define SCAN_SUBSTEP(EIN, EOUT, TT)                                                      \
        {                                                                                \
            const int p_ = ((TT) >> 5) & 1;                                              \
            const int st = (TT) & 31;                                                    \
            if (st == 0) barsync(3 + p_);                                                \
            {   const int ft = (TT) + 15;                                                \
                if (ft < T) {                                                            \
                    uint32_t sb = ring_b + (ft & 15)*1024 + lane*16;                     \
                    const float* gp = Lrow + (size_t)ft*256 + lane*4;                    \
                    cp16(sb, gp);                                                        \
                    cp16(sb + 512, gp + 128);                                            \
                    if (lane < 4) cp16(gring_b + (ft & 15)*64 + lane*16,                 \
                                       grow + (size_t)ft*16 + lane*4);                   \
                }                                                                        \
                cpcommit();                                                              \
            }                                                                            \
            /* half matvec: this lane covers rows kbase..kbase+7 of column j */          \
            float u0 = EIN[0]*Lc[0], u1 = EIN[1]*Lc[1];                                  \
            u0 = fmaf(EIN[2], Lc[2], u0); u1 = fmaf(EIN[3], Lc[3], u1);                  \
            u0 = fmaf(EIN[4], Lc[4], u0); u1 = fmaf(EIN[5], Lc[5], u1);                  \
            u0 = fmaf(EIN[6], Lc[6], u0); u1 = fmaf(EIN[7], Lc[7], u1);                  \
            const float up = u0 + u1;                                                    \
            const float u  = up + __shfl_xor_sync(FMASK, up, 16);                        \
            const float x  = fmaf(u, rC, gC);                                            \
            const float en = ex2f(x);                                                    \
            /* broadcast: this lane needs e_{kbase..kbase+7} for next matvec */          \
            _Pragma("unroll")                                                            \
            for (int i = 0; i < 8; ++i) EOUT[i] = __shfl_sync(FMASK, en, kbase + i);     \
            if (wr) { ebuf[(p_*32 + st)*16 + j] = en;                                    \
                      ubuf[(p_*32 + st)*16 + j] = u; }                                   \
            cpwait14();                                                                  \
            __syncwarp();                                                                \
            {   const int s1 = ((TT) + 1) & 15;                                          \
                _Pragma("unroll")                                                        \
                for (int i = 0; i < 8; ++i) Lc[i] = ring[s1*256 + (kbase + i)*16 + j];   \
                gC = gring[s1*16 + j] * SCALE;                                           \
            }                                                                            \
            /* S = sum over all 16 e: own-half tree + cross-half bfly */                 \
            const float sA = (EOUT[0]+EOUT[1])+(EOUT[2]+EOUT[3]);                        \
            const float sB = (EOUT[4]+EOUT[5])+(EOUT[6]+EOUT[7]);                        \
            const float hs = sA + sB;                                                    \
            const float S  = hs + __shfl_xor_sync(FMASK, hs, 16);                        \
            const float r  = rcpf(S);                                                    \
            rC = r * SCALE;                                                              \
            if (lane == 0) rbuf[p_*32 + st] = r;                                         \
            if (st == 31) { membar_cta(); bararrive(1 + p_); }                           \
        }

        for (int t = 0; t < T; t += 2) {
            SCAN_SUBSTEP(ea, eb, t)
            SCAN_SUBSTEP(eb, ea, t + 1)
        }
#undef SCAN_SUBSTEP
    } else if (w == 0) {
        // ---------------- scalar warp (lq, lp), SMSP0, lane-per-timestep ----------------
        bararrive(3); bararrive(4);   // prime empty barriers

        float* lgP = (float*)lgPs4;
        for (int i = lane; i < 256; i += 32) lgP[i] = logf(transP[i]);
        __syncwarp();

        for (int i = tid; i < 512; i += 224) outC[b*512 + i] = Cmat[i];

        const int s = lane;
        const int sm = (s == 0) ? 0 : (s - 1);
        float epv[16];                 // carried e of step t-1 for lane 0
        #pragma unroll
        for (int k = 0; k < 16; ++k) epv[k] = 1.0f;
        float rpv = 0.0625f;           // carried r_{t-1} for lane 0 (chunk boundary)

        for (int c = 0; c < 32; ++c) {
            const int p = c & 1;
            barsync(1 + p);   // wait chunk full
            const int t = c*32 + s;

            const float4* eb4  = reinterpret_cast<const float4*>(&ebuf[(p*32 + s)*16]);
            const float4* eb4m = reinterpret_cast<const float4*>(&ebuf[(p*32 + sm)*16]);
            const float4* ub4  = reinterpret_cast<const float4*>(&ubuf[(p*32 + s)*16]);
            float es[16], ep[16], us[16];
            {
                const float4 a0 = eb4[0], a1 = eb4[1], a2 = eb4[2], a3 = eb4[3];
                es[0]=a0.x; es[1]=a0.y; es[2]=a0.z; es[3]=a0.w;
                es[4]=a1.x; es[5]=a1.y; es[6]=a1.z; es[7]=a1.w;
                es[8]=a2.x; es[9]=a2.y; es[10]=a2.z; es[11]=a2.w;
                es[12]=a3.x; es[13]=a3.y; es[14]=a3.z; es[15]=a3.w;
                const float4 b0 = ub4[0], b1 = ub4[1], b2 = ub4[2], b3 = ub4[3];
                us[0]=b0.x; us[1]=b0.y; us[2]=b0.z; us[3]=b0.w;
                us[4]=b1.x; us[5]=b1.y; us[6]=b1.z; us[7]=b1.w;
                us[8]=b2.x; us[9]=b2.y; us[10]=b2.z; us[11]=b2.w;
                us[12]=b3.x; us[13]=b3.y; us[14]=b3.z; us[15]=b3.w;
                const float4 c0 = eb4m[0], c1 = eb4m[1], c2 = eb4m[2], c3 = eb4m[3];
                float em[16];
                em[0]=c0.x; em[1]=c0.y; em[2]=c0.z; em[3]=c0.w;
                em[4]=c1.x; em[5]=c1.y; em[6]=c1.z; em[7]=c1.w;
                em[8]=c2.x; em[9]=c2.y; em[10]=c2.z; em[11]=c2.w;
                em[12]=c3.x; em[13]=c3.y; em[14]=c3.z; em[15]=c3.w;
                #pragma unroll
                for (int k = 0; k < 16; ++k) ep[k] = (s == 0) ? epv[k] : em[k];
            }
            const float rs = rbuf[p*32 + s];
            const float rm = (s == 0) ? rpv : rbuf[p*32 + sm];

            // y = es*rs ; l = us*rm ; yprev = ep*rm
            float dd = 0.0f, ee = 0.0f;
            float yj[16], lj[16];
            #pragma unroll
            for (int k = 0; k < 16; ++k) {
                lj[k] = us[k] * rm;
                yj[k] = es[k] * rs;
                dd = fmaf(yj[k], lj[k], dd);
                ee += ex2f(lj[k] * LOG2E);
            }
            const float lq = dd - lg2f(ee) * LN2;

            float acc = 0.0f;
            #pragma unroll
            for (int i = 0; i < 16; ++i) {
                const float4 r0 = lgPs4[i*4+0], r1 = lgPs4[i*4+1];
                const float4 r2 = lgPs4[i*4+2], r3 = lgPs4[i*4+3];
                float wv =        yj[0]*r0.x;
                wv = fmaf(yj[1],  r0.y, wv); wv = fmaf(yj[2],  r0.z, wv); wv = fmaf(yj[3],  r0.w, wv);
                wv = fmaf(yj[4],  r1.x, wv); wv = fmaf(yj[5],  r1.y, wv); wv = fmaf(yj[6],  r1.z, wv);
                wv = fmaf(yj[7],  r1.w, wv); wv = fmaf(yj[8],  r2.x, wv); wv = fmaf(yj[9],  r2.y, wv);
                wv = fmaf(yj[10], r2.z, wv); wv = fmaf(yj[11], r2.w, wv); wv = fmaf(yj[12], r3.x, wv);
                wv = fmaf(yj[13], r3.y, wv); wv = fmaf(yj[14], r3.z, wv); wv = fmaf(yj[15], r3.w, wv);
                acc = fmaf(ep[i] * rm, wv, acc);
            }
            const float lp = (t == 0) ? -2.7725887222397811f : acc;  // -log(16) at t=0

            outLq[(size_t)b*T + t] = lq;
            outLp[(size_t)b*T + t] = lp;

            // carry lane-31 state (e_t, r_t) for next chunk's lane 0
            #pragma unroll
            for (int k = 0; k < 16; ++k) epv[k] = __shfl_sync(FMASK, es[k], 31);
            rpv = __shfl_sync(FMASK, rs, 31);

            bararrive(3 + p);   // chunk empty
        }
    } else {
        // ---------------- A/B expansion warps ----------------
        bararrive(3); bararrive(4);   // prime empty barriers

        const bool isA = (w == 1 || w == 2 || w == 5 || w == 6);
        float Mc0[16], Mc1[16];
        int eidx;
        float* outM;
        int stride;
        if (isA) {
            const int aw = (w < 4) ? (w - 1) : (w - 3);   // w1->0, w2->1, w5->2, w6->3
            eidx = (aw*32 + lane)*2;
            #pragma unroll
            for (int k = 0; k < 16; ++k) { Mc0[k] = Amat[k*256 + eidx]; Mc1[k] = Amat[k*256 + eidx + 1]; }
            outM = outA; stride = 256;
        } else {
            const int bw = (w == 3) ? 0 : 1;
            eidx = (bw*32 + lane)*2;
            #pragma unroll
            for (int k = 0; k < 16; ++k) { Mc0[k] = Bmat[k*128 + eidx]; Mc1[k] = Bmat[k*128 + eidx + 1]; }
            outM = outB; stride = 128;
        }

        for (int i = (w < 4 ? tid : tid - 32); i < 512; i += 224) outC[b*512 + i] = Cmat[i];

        for (int c = 0; c < 32; ++c) {
            const int p = c & 1;
            barsync(1 + p);   // wait chunk full
            #pragma unroll 4
            for (int s = 0; s < 32; ++s) {
                const int t = c*32 + s;
                const float4* yb4 = reinterpret_cast<const float4*>(&ebuf[(p*32 + s)*16]);
                const float4 v0 = yb4[0], v1 = yb4[1], v2 = yb4[2], v3 = yb4[3];
                const float r = rbuf[p*32 + s];
                const float ya[16] = {v0.x,v0.y,v0.z,v0.w, v1.x,v1.y,v1.z,v1.w,
                                      v2.x,v2.y,v2.z,v2.w, v3.x,v3.y,v3.z,v3.w};
                float a0 = ya[0]*Mc0[0], a1 = ya[0]*Mc1[0];
                #pragma unroll
                for (int k = 1; k < 16; ++k) { a0 = fmaf(ya[k], Mc0[k], a0); a1 = fmaf(ya[k], Mc1[k], a1); }
                *reinterpret_cast<float2*>(outM + ((size_t)b*T + t)*stride + eidx) =
                    make_float2(a0 * r, a1 * r);
            }
            bararrive(3 + p);   // chunk empty
        }
    }
}

extern "C" void kernel_launch(void* const* d_in, const int* in_sizes, int n_in,
                              void* d_out, int out_size)
{
    const float *logits = nullptr, *gum = nullptr, *A = nullptr, *Bm = nullptr,
                *Cm = nullptr, *tP = nullptr;
    for (int i = 0; i < n_in; ++i) {
        switch (in_sizes[i]) {
            case 33554432: logits = (const float*)d_in[i]; break;  // (128,1024,16,16)
            case 2097152:  gum    = (const float*)d_in[i]; break;  // (128,1024,16)
            case 4096:     A      = (const float*)d_in[i]; break;  // (16,16,16)
            case 2048:     Bm     = (const float*)d_in[i]; break;  // (16,16,8)
            case 8192:     Cm     = (const float*)d_in[i]; break;  // (16,32,16)
            case 256:      tP     = (const float*)d_in[i]; break;  // (16,16)
        }
    }
    (void)out_size;
    dynparam_kernel<<<128, 256>>>(logits, gum, A, Bm, Cm, tP, (float*)d_out);
}

// round 6
// speedup vs baseline: 1.0474x; 1.0474x over previous
#include <cuda_runtime.h>
#include <stdint.h>
#include <math.h>

#define FMASK 0xffffffffu

static __device__ __forceinline__ float ex2f(float x){ float y; asm("ex2.approx.f32 %0, %1;" : "=f"(y) : "f"(x)); return y; }
static __device__ __forceinline__ float lg2f(float x){ float y; asm("lg2.approx.f32 %0, %1;" : "=f"(y) : "f"(x)); return y; }
static __device__ __forceinline__ float rcpf(float x){ float y; asm("rcp.approx.f32 %0, %1;" : "=f"(y) : "f"(x)); return y; }
static __device__ __forceinline__ void cp16(uint32_t dst, const void* src){
    asm volatile("cp.async.cg.shared.global [%0], [%1], 16;" :: "r"(dst), "l"(src) : "memory");
}
static __device__ __forceinline__ void cpcommit(){ asm volatile("cp.async.commit_group;" ::: "memory"); }
static __device__ __forceinline__ void cpwait14(){ asm volatile("cp.async.wait_group 14;" ::: "memory"); }

// packed f32x2 helpers (FFMA2 path — only reachable via PTX)
static __device__ __forceinline__ unsigned long long dup2(float x){
    unsigned long long r; asm("mov.b64 %0, {%1, %1};" : "=l"(r) : "f"(x)); return r;
}
static __device__ __forceinline__ unsigned long long pk2(float lo, float hi){
    unsigned long long r; asm("mov.b64 %0, {%1, %2};" : "=l"(r) : "f"(lo), "f"(hi)); return r;
}
static __device__ __forceinline__ unsigned long long fma2(unsigned long long a, unsigned long long b, unsigned long long c){
    unsigned long long d; asm("fma.rn.f32x2 %0, %1, %2, %3;" : "=l"(d) : "l"(a), "l"(b), "l"(c)); return d;
}
static __device__ __forceinline__ unsigned long long mul2(unsigned long long a, unsigned long long b){
    unsigned long long d; asm("mul.rn.f32x2 %0, %1, %2;" : "=l"(d) : "l"(a), "l"(b)); return d;
}
static __device__ __forceinline__ float2 unpk2(unsigned long long v){
    float2 f; asm("mov.b64 {%0, %1}, %2;" : "=f"(f.x), "=f"(f.y) : "l"(v)); return f;
}

// Scratch: raw scan state (allocation-free __device__ globals)
__device__ float g_e[128*1024*16];   // unnormalized softmax numerators e_t
__device__ float g_u[128*1024*16];   // raw mixed logits u_t (l_t = u_t * r_{t-1})
__device__ float g_r[128*1024];      // r_t = 1/S_t  (y_t = e_t * r_t)

// ============================================================================
// Kernel 1: scan — 1 warp per CTA, one batch row. Pure recurrence chain.
// ============================================================================
__global__ __launch_bounds__(32, 1)
void scan_kernel(const float* __restrict__ logits,
                 const float* __restrict__ gum)
{
    constexpr int T = 1024;
    constexpr float SCALE = 2.8853900817779268f;   // (1/tau)*log2(e), tau = 0.5

    __shared__ __align__(16) float ring[16*256];   // logits ring, 16 slots (15 ahead)
    __shared__ __align__(16) float gring[16*16];   // gumbel ring

    const int b = blockIdx.x;
    const int lane = threadIdx.x;
    const int j = lane & 15;
    const bool wr = (lane < 16);

    const float* Lrow = logits + (size_t)b * ((size_t)T * 256);
    const float* grow = gum    + (size_t)b * ((size_t)T * 16);
    float* pe = g_e + (size_t)b * (T * 16);
    float* pu = g_u + (size_t)b * (T * 16);
    float* pr = g_r + (size_t)b * T;
    uint32_t ring_b  = (uint32_t)__cvta_generic_to_shared(ring);
    uint32_t gring_b = (uint32_t)__cvta_generic_to_shared(gring);

    // prologue: prefetch steps 0..14
    #pragma unroll
    for (int pt = 0; pt < 15; ++pt) {
        uint32_t sb = ring_b + pt*1024 + lane*16;
        const float* gp = Lrow + pt*256 + lane*4;
        cp16(sb, gp);
        cp16(sb + 512, gp + 128);
        if (lane < 4) cp16(gring_b + pt*64 + lane*16, grow + pt*16 + lane*4);
        cpcommit();
    }
    cpwait14();            // slot 0 complete
    __syncwarp();

    float Lc[16], ea[16], eb[16];
    #pragma unroll
    for (int k = 0; k < 16; ++k) { Lc[k] = ring[k*16 + j]; ea[k] = 1.0f; }
    float gC = gring[j] * SCALE;
    float rC = 0.0625f * SCALE;   // SCALE * r_{-1}  (y0 uniform)

#define SCAN_SUBSTEP(EIN, EOUT, TT)                                                      \
    {                                                                                    \
        {   const int ft = (TT) + 15;                                                    \
            if (ft < T) {                                                                \
                uint32_t sb = ring_b + (ft & 15)*1024 + lane*16;                         \
                const float* gp = Lrow + (size_t)ft*256 + lane*4;                        \
                cp16(sb, gp);                                                            \
                cp16(sb + 512, gp + 128);                                                \
                if (lane < 4) cp16(gring_b + (ft & 15)*64 + lane*16,                     \
                                   grow + (size_t)ft*16 + lane*4);                       \
            }                                                                            \
            cpcommit();                                                                  \
        }                                                                                \
        float u0 = EIN[0]*Lc[0], u1 = EIN[1]*Lc[1], u2 = EIN[2]*Lc[2], u3 = EIN[3]*Lc[3];\
        _Pragma("unroll")                                                                \
        for (int k = 4; k < 16; k += 4) {                                                \
            u0 = fmaf(EIN[k+0], Lc[k+0], u0);                                            \
            u1 = fmaf(EIN[k+1], Lc[k+1], u1);                                            \
            u2 = fmaf(EIN[k+2], Lc[k+2], u2);                                            \
            u3 = fmaf(EIN[k+3], Lc[k+3], u3);                                            \
        }                                                                                \
        const float u = (u0+u1)+(u2+u3);                                                 \
        const float x = fmaf(u, rC, gC);                                                 \
        const float en = ex2f(x);                                                        \
        _Pragma("unroll")                                                                \
        for (int k = 0; k < 16; ++k) EOUT[k] = __shfl_sync(FMASK, en, k);                \
        if (wr) { pe[(TT)*16 + j] = en; pu[(TT)*16 + j] = u; }                           \
        cpwait14();                                                                      \
        __syncwarp();                                                                    \
        {   const int s1 = ((TT) + 1) & 15;                                              \
            _Pragma("unroll")                                                            \
            for (int k = 0; k < 16; ++k) Lc[k] = ring[s1*256 + k*16 + j];                \
            gC = gring[s1*16 + j] * SCALE;                                               \
        }                                                                                \
        const float sA = (EOUT[0]+EOUT[1])+(EOUT[2]+EOUT[3]);                            \
        const float sB = (EOUT[4]+EOUT[5])+(EOUT[6]+EOUT[7]);                            \
        const float sC = (EOUT[8]+EOUT[9])+(EOUT[10]+EOUT[11]);                          \
        const float sD = (EOUT[12]+EOUT[13])+(EOUT[14]+EOUT[15]);                        \
        const float S = (sA+sB)+(sC+sD);                                                 \
        const float r = rcpf(S);                                                         \
        rC = r * SCALE;                                                                  \
        if (lane == 0) pr[TT] = r;                                                       \
    }

    for (int t = 0; t < T; t += 2) {
        SCAN_SUBSTEP(ea, eb, t)
        SCAN_SUBSTEP(eb, ea, t + 1)
    }
#undef SCAN_SUBSTEP
}

// ============================================================================
// Kernel 2: expansion — A_seq = y·A, B_seq = y·Bm. Bandwidth-bound, f32x2 FMA.
// grid (16 tiles, 128 b), 384 threads: tsub = tid/96 handles t = tile*64+tt*4+tsub,
// e96 = tid%96 owns one float4 of the 384-float output row (64 for A, 32 for B).
// ============================================================================
__global__ __launch_bounds__(384, 1)
void expand_kernel(const float* __restrict__ Amat,
                   const float* __restrict__ Bmat,
                   float* __restrict__ out)
{
    __shared__ __align__(16) float es[64*16];
    __shared__ float rs[64];

    const int b = blockIdx.y;
    const int t0 = blockIdx.x * 64;
    const int tid = threadIdx.x;
    const int tsub = tid / 96;
    const int e96 = tid % 96;

    float* outA = out;                // (B,T,16,16)
    float* outB = out + 33554432u;    // (B,T,16,8)

    // own output column block: M[k] packed as f32x2 pairs
    unsigned long long M[32];
    const float* Msrc;
    int stride, base;
    if (e96 < 64) { const int i = e96 >> 2, jc = (e96 & 3) * 4; base = i*16 + jc; stride = 256; Msrc = Amat; }
    else          { const int q = e96 - 64; const int i = q >> 1, jc = (q & 1) * 4; base = i*8 + jc; stride = 128; Msrc = Bmat; }
    #pragma unroll
    for (int k = 0; k < 16; ++k) {
        const float4 v = *reinterpret_cast<const float4*>(Msrc + k*stride + base);
        M[2*k]   = pk2(v.x, v.y);
        M[2*k+1] = pk2(v.z, v.w);
    }

    // stage tile of e (64x16) and r (64)
    const float* esrc = g_e + ((size_t)b*1024 + t0) * 16;
    if (tid < 256) *reinterpret_cast<float4*>(&es[tid*4]) = *reinterpret_cast<const float4*>(&esrc[tid*4]);
    if (tid >= 320) rs[tid - 320] = g_r[(size_t)b*1024 + t0 + (tid - 320)];
    __syncthreads();

    float* outp = ((e96 < 64) ? outA : outB) + ((size_t)b*1024 + t0) * (size_t)stride + base;

    #pragma unroll 4
    for (int tt = 0; tt < 16; ++tt) {
        const int tl = tt*4 + tsub;
        const float4* ep4 = reinterpret_cast<const float4*>(&es[tl*16]);
        const float4 y0 = ep4[0], y1 = ep4[1], y2 = ep4[2], y3 = ep4[3];
        unsigned long long d[16];
        d[0]=dup2(y0.x); d[1]=dup2(y0.y); d[2]=dup2(y0.z); d[3]=dup2(y0.w);
        d[4]=dup2(y1.x); d[5]=dup2(y1.y); d[6]=dup2(y1.z); d[7]=dup2(y1.w);
        d[8]=dup2(y2.x); d[9]=dup2(y2.y); d[10]=dup2(y2.z); d[11]=dup2(y2.w);
        d[12]=dup2(y3.x); d[13]=dup2(y3.y); d[14]=dup2(y3.z); d[15]=dup2(y3.w);
        unsigned long long a0 = mul2(d[0], M[0]);
        unsigned long long a1 = mul2(d[0], M[1]);
        #pragma unroll
        for (int k = 1; k < 16; ++k) {
            a0 = fma2(d[k], M[2*k],   a0);
            a1 = fma2(d[k], M[2*k+1], a1);
        }
        const unsigned long long rd = dup2(rs[tl]);
        a0 = mul2(a0, rd);
        a1 = mul2(a1, rd);
        const float2 f0 = unpk2(a0), f1 = unpk2(a1);
        *reinterpret_cast<float4*>(outp + (size_t)tl * stride) = make_float4(f0.x, f0.y, f1.x, f1.y);
    }
}

// ============================================================================
// Kernel 3: scalars — lq, lp, C_seq. grid (8, 128), 128 threads, 1 thread = 1 t.
// ============================================================================
__global__ __launch_bounds__(128, 1)
void scalars_kernel(const float* __restrict__ transP,
                    const float* __restrict__ Cmat,
                    float* __restrict__ out)
{
    constexpr float LOG2E = 1.4426950408889634f;
    constexpr float LN2   = 0.6931471805599453f;
    __shared__ __align__(16) float lgP[256];

    const int b = blockIdx.y;
    const int tid = threadIdx.x;
    const int t = blockIdx.x * 128 + tid;

    float* outC  = out + 50331648u;   // (B,1,32,16)
    float* outLq = out + 50397184u;   // (B,T)
    float* outLp = out + 50528256u;   // (B,T)

    lgP[tid] = logf(transP[tid]);
    lgP[tid + 128] = logf(transP[tid + 128]);
    if (blockIdx.x == 0) {
        #pragma unroll
        for (int i = tid; i < 512; i += 128) outC[b*512 + i] = Cmat[i];
    }
    __syncthreads();

    const size_t bt = (size_t)b*1024 + t;
    float es[16], us[16], ep[16];
    {
        const float4* e4 = reinterpret_cast<const float4*>(g_e + bt*16);
        const float4* u4 = reinterpret_cast<const float4*>(g_u + bt*16);
        #pragma unroll
        for (int q = 0; q < 4; ++q) {
            const float4 ev = e4[q], uv = u4[q];
            es[q*4+0]=ev.x; es[q*4+1]=ev.y; es[q*4+2]=ev.z; es[q*4+3]=ev.w;
            us[q*4+0]=uv.x; us[q*4+1]=uv.y; us[q*4+2]=uv.z; us[q*4+3]=uv.w;
        }
    }
    const float rt = g_r[bt];
    float rm;
    if (t == 0) {
        rm = 0.0625f;
        #pragma unroll
        for (int k = 0; k < 16; ++k) ep[k] = 1.0f;
    } else {
        rm = g_r[bt - 1];
        const float4* p4 = reinterpret_cast<const float4*>(g_e + (bt - 1)*16);
        #pragma unroll
        for (int q = 0; q < 4; ++q) {
            const float4 pv = p4[q];
            ep[q*4+0]=pv.x; ep[q*4+1]=pv.y; ep[q*4+2]=pv.z; ep[q*4+3]=pv.w;
        }
    }

    // y = es*rt, l = us*rm, yprev = ep*rm
    float yj[16], lj[16];
    float dd = 0.0f, ee = 0.0f;
    #pragma unroll
    for (int k = 0; k < 16; ++k) {
        yj[k] = es[k] * rt;
        lj[k] = us[k] * rm;
        dd = fmaf(yj[k], lj[k], dd);
        ee += ex2f(lj[k] * LOG2E);
    }
    const float lq = dd - lg2f(ee) * LN2;

    const float4* P4 = reinterpret_cast<const float4*>(lgP);
    float acc = 0.0f;
    #pragma unroll
    for (int i = 0; i < 16; ++i) {
        const float4 r0 = P4[i*4+0], r1 = P4[i*4+1], r2 = P4[i*4+2], r3 = P4[i*4+3];
        float wv =        yj[0]*r0.x;
        wv = fmaf(yj[1],  r0.y, wv); wv = fmaf(yj[2],  r0.z, wv); wv = fmaf(yj[3],  r0.w, wv);
        wv = fmaf(yj[4],  r1.x, wv); wv = fmaf(yj[5],  r1.y, wv); wv = fmaf(yj[6],  r1.z, wv);
        wv = fmaf(yj[7],  r1.w, wv); wv = fmaf(yj[8],  r2.x, wv); wv = fmaf(yj[9],  r2.y, wv);
        wv = fmaf(yj[10], r2.z, wv); wv = fmaf(yj[11], r2.w, wv); wv = fmaf(yj[12], r3.x, wv);
        wv = fmaf(yj[13], r3.y, wv); wv = fmaf(yj[14], r3.z, wv); wv = fmaf(yj[15], r3.w, wv);
        acc = fmaf(ep[i] * rm, wv, acc);
    }
    const float lp = (t == 0) ? -2.7725887222397811f : acc;   // -log(16) at t=0

    outLq[bt] = lq;
    outLp[bt] = lp;
}

extern "C" void kernel_launch(void* const* d_in, const int* in_sizes, int n_in,
                              void* d_out, int out_size)
{
    const float *logits = nullptr, *gum = nullptr, *A = nullptr, *Bm = nullptr,
                *Cm = nullptr, *tP = nullptr;
    for (int i = 0; i < n_in; ++i) {
        switch (in_sizes[i]) {
            case 33554432: logits = (const float*)d_in[i]; break;  // (128,1024,16,16)
            case 2097152:  gum    = (const float*)d_in[i]; break;  // (128,1024,16)
            case 4096:     A      = (const float*)d_in[i]; break;  // (16,16,16)
            case 2048:     Bm     = (const float*)d_in[i]; break;  // (16,16,8)
            case 8192:     Cm     = (const float*)d_in[i]; break;  // (16,32,16)
            case 256:      tP     = (const float*)d_in[i]; break;  // (16,16)
        }
    }
    (void)out_size;
    float* outp = (float*)d_out;
    scan_kernel<<<128, 32>>>(logits, gum);
    expand_kernel<<<dim3(16, 128), 384>>>(A, Bm, outp);
    scalars_kernel<<<dim3(8, 128), 128>>>(tP, Cm, outp);
}